// round 3
// baseline (speedup 1.0000x reference)
#include <cuda_runtime.h>
#include <cuda_bf16.h>
#include <cstdint>

#define N_NODES 50000
#define N_EDGES 800000
#define NUM_GRAPHS 512

// ---------------- scratch (no allocations allowed) ----------------
__device__ __align__(16) float g_h0[N_NODES * 64];
__device__ __align__(16) float g_h1[N_NODES * 64];
__device__ __align__(16) float g_h2[N_NODES * 128];
__device__ __align__(16) float g_h3[N_NODES * 128];
__device__ __align__(16) float g_agg[N_NODES * 128];
__device__ __align__(16) float g_pool[NUM_GRAPHS * 128];
__device__ int   g_cnt[NUM_GRAPHS];
__device__ int   g_src[N_EDGES];
__device__ int   g_dst[N_EDGES];
__device__ int   g_batch[N_NODES];

// Resolve buffer id -> device global (device-side only).
__device__ __forceinline__ float* buf_ptr(int id) {
    switch (id) {
        case 0: return g_h0;
        case 1: return g_h1;
        case 2: return g_h2;
        case 3: return g_h3;
        default: return g_agg;
    }
}

// ---------------- index conversion with on-device dtype detection ------------
// If the buffer holds int64 values < 2^31, every odd 32-bit word is zero.
// Edge buffer: random values in [0,50000) -> test odd words 1..31 (first 32
// words; safe: both dtypes have >= E words). batch is SORTED (leading zeros
// are legit int32 values), so test odd words at the END of the first N words,
// where int32 values ~511 != 0. All probe reads stay within the smaller
// (int32) buffer size.
__global__ void convert_edges_kernel(const void* __restrict__ ei_raw, int E) {
    const int* w = (const int*)ei_raw;
    bool is64 = true;
#pragma unroll
    for (int j = 1; j < 32; j += 2) is64 &= (w[j] == 0);
    int i = blockIdx.x * blockDim.x + threadIdx.x;
    if (i >= E) return;
    if (is64) {
        const long long* e64 = (const long long*)ei_raw;
        g_src[i] = (int)e64[i];
        g_dst[i] = (int)e64[E + i];
    } else {
        g_src[i] = w[i];
        g_dst[i] = w[E + i];
    }
}

__global__ void convert_batch_kernel(const void* __restrict__ b_raw, int N) {
    const int* w = (const int*)b_raw;
    bool is64 = true;
#pragma unroll
    for (int j = 1; j < 32; j += 2) is64 &= (w[N - 1 - j] == 0 || ((N - 1 - j) & 1) == 0)
                                            ? (((N - 1 - j) & 1) ? w[N - 1 - j] == 0 : true)
                                            : false;
    // simpler, explicit: odd-index words among the last 32 of the first N words
    is64 = true;
#pragma unroll
    for (int j = 0; j < 32; ++j) {
        int idx = N - 32 + j;
        if (idx & 1) is64 &= (w[idx] == 0);
    }
    int i = blockIdx.x * blockDim.x + threadIdx.x;
    if (i >= N) return;
    if (is64) g_batch[i] = (int)((const long long*)b_raw)[i];
    else      g_batch[i] = w[i];
}

// ---------------- kernels ----------------

__global__ void zero_agg_kernel(int n4) {
    int i = blockIdx.x * blockDim.x + threadIdx.x;
    if (i < n4) ((float4*)g_agg)[i] = make_float4(0.f, 0.f, 0.f, 0.f);
}

__global__ void zero_pool_kernel() {
    int i = blockIdx.x * blockDim.x + threadIdx.x;
    if (i < NUM_GRAPHS * 128) g_pool[i] = 0.f;
    if (i < NUM_GRAPHS) g_cnt[i] = 0;
}

// Generic fused GEMM: out[M,N] = relu?( A@Wa + (B? B@Wb : 0) + bias )
// One thread per node row; 64 output columns per thread (blockIdx.y picks half).
__global__ void __launch_bounds__(256)
fused_gemm_kernel(const float* __restrict__ x_ext, int aId, int bId,
                  const float* __restrict__ Wa, const float* __restrict__ Wb,
                  const float* __restrict__ bias, int outId,
                  int M, int K, int N, int doRelu) {
    __shared__ __align__(16) float tile[64][64];
    const float* A = (aId < 0) ? x_ext : buf_ptr(aId);
    float* out = buf_ptr(outId);
    int node = blockIdx.x * blockDim.x + threadIdx.x;
    int colbase = blockIdx.y * 64;

    float acc[64];
#pragma unroll
    for (int n = 0; n < 64; n++) acc[n] = bias[colbase + n];

    int npasses = (bId >= 0) ? 2 : 1;
    for (int pass = 0; pass < npasses; ++pass) {
        const float* X = pass ? buf_ptr(bId) : A;
        const float* W = pass ? Wb : Wa;
        for (int kc = 0; kc < K; kc += 64) {
            __syncthreads();
            for (int i = threadIdx.x; i < 64 * 64; i += 256) {
                int kk = i >> 6, j = i & 63;
                tile[kk][j] = W[(size_t)(kc + kk) * N + colbase + j];
            }
            __syncthreads();
            if (node < M) {
                const float4* xrow = (const float4*)(X + (size_t)node * K + kc);
#pragma unroll
                for (int k4 = 0; k4 < 16; ++k4) {
                    float4 a = xrow[k4];
                    float av[4] = {a.x, a.y, a.z, a.w};
#pragma unroll
                    for (int kk = 0; kk < 4; ++kk) {
                        const float4* wrow = (const float4*)tile[k4 * 4 + kk];
                        float v = av[kk];
#pragma unroll
                        for (int n4 = 0; n4 < 16; ++n4) {
                            float4 w = wrow[n4];
                            acc[n4 * 4 + 0] += v * w.x;
                            acc[n4 * 4 + 1] += v * w.y;
                            acc[n4 * 4 + 2] += v * w.z;
                            acc[n4 * 4 + 3] += v * w.w;
                        }
                    }
                }
            }
        }
    }
    if (node < M) {
        float4* orow = (float4*)(out + (size_t)node * N + colbase);
#pragma unroll
        for (int n4 = 0; n4 < 16; ++n4) {
            float4 v = make_float4(acc[n4 * 4 + 0], acc[n4 * 4 + 1],
                                   acc[n4 * 4 + 2], acc[n4 * 4 + 3]);
            if (doRelu) {
                v.x = fmaxf(v.x, 0.f); v.y = fmaxf(v.y, 0.f);
                v.z = fmaxf(v.z, 0.f); v.w = fmaxf(v.w, 0.f);
            }
            orow[n4] = v;
        }
    }
}

// Edge scatter-add: g_agg[dst] += h[src], float4 global reductions.
__global__ void scatter_kernel(int hId, int E, int dimv, int lg) {
    int idx = blockIdx.x * blockDim.x + threadIdx.x;
    if (idx >= E * dimv) return;
    const float* h = buf_ptr(hId);
    int e = idx >> lg;
    int c = idx & (dimv - 1);
    int s = g_src[e];
    int d = g_dst[e];
    float4 v = ((const float4*)h)[(size_t)s * dimv + c];
    float* p = g_agg + (((size_t)d * dimv + c) << 2);
    asm volatile("red.global.add.v4.f32 [%0], {%1, %2, %3, %4};"
                 :: "l"(p), "f"(v.x), "f"(v.y), "f"(v.z), "f"(v.w) : "memory");
}

__global__ void count_kernel(int N) {
    int i = blockIdx.x * blockDim.x + threadIdx.x;
    if (i < N) atomicAdd(&g_cnt[g_batch[i]], 1);
}

// Mean-pool accumulation over g_h3 (dim=128 -> 32 float4 per node).
__global__ void pool_kernel(int N) {
    int idx = blockIdx.x * blockDim.x + threadIdx.x;
    if (idx >= N * 32) return;
    int node = idx >> 5;
    int c = idx & 31;
    int g = g_batch[node];
    float4 v = ((const float4*)g_h3)[(size_t)node * 32 + c];
    float* p = g_pool + (((size_t)g * 32 + c) << 2);
    asm volatile("red.global.add.v4.f32 [%0], {%1, %2, %3, %4};"
                 :: "l"(p), "f"(v.x), "f"(v.y), "f"(v.z), "f"(v.w) : "memory");
}

// out[g,c] = lin_b[c] + sum_k (pool[g,k]/cnt[g]) * lin_w[k,c]
__global__ void final_kernel(const float* __restrict__ lw, const float* __restrict__ lb,
                             float* __restrict__ out) {
    int g = blockIdx.x;
    int c = threadIdx.x;  // 16
    float inv = 1.f / fmaxf((float)g_cnt[g], 1.f);
    float acc = lb[c];
#pragma unroll 8
    for (int k = 0; k < 128; ++k)
        acc += g_pool[g * 128 + k] * inv * lw[k * 16 + c];
    out[g * 16 + c] = acc;
}

// ---------------- launch ----------------
extern "C" void kernel_launch(void* const* d_in, const int* in_sizes, int n_in,
                              void* d_out, int out_size) {
    const float* x     = (const float*)d_in[0];
    const void*  ei    = d_in[1];
    const void*  batch = d_in[2];
    // num_graphs may or may not be materialized as a tiny input; detect.
    int wi = (in_sizes[3] < 100) ? 4 : 3;
    const float* w_stage1 = (const float*)d_in[wi + 0];
    const float* b_stage1 = (const float*)d_in[wi + 1];
    const float* rel1_w   = (const float*)d_in[wi + 2];
    const float* rel1_b   = (const float*)d_in[wi + 3];
    const float* root1_w  = (const float*)d_in[wi + 4];
    const float* rel2_w   = (const float*)d_in[wi + 5];
    const float* rel2_b   = (const float*)d_in[wi + 6];
    const float* root2_w  = (const float*)d_in[wi + 7];
    const float* rel3_w   = (const float*)d_in[wi + 8];
    const float* rel3_b   = (const float*)d_in[wi + 9];
    const float* root3_w  = (const float*)d_in[wi + 10];
    const float* lin_w    = (const float*)d_in[wi + 11];
    const float* lin_b    = (const float*)d_in[wi + 12];
    float* out = (float*)d_out;

    const int M = N_NODES, E = N_EDGES;

    // index conversion (dtype-detecting)
    convert_edges_kernel<<<(E + 255) / 256, 256>>>(ei, E);
    convert_batch_kernel<<<(M + 255) / 256, 256>>>(batch, M);

    // stage1: h0 = x @ w_stage1 + b_stage1   [M,128]x[128,64] -> buf 0
    {
        dim3 grid((M + 255) / 256, 1);
        fused_gemm_kernel<<<grid, 256>>>(x, -1, -1, w_stage1, nullptr,
                                         b_stage1, 0, M, 128, 64, 0);
    }

    // layer 1: agg(h0,64) ; h1 = relu(agg@rel1_w + rel1_b + h0@root1_w) -> buf 1
    zero_agg_kernel<<<(M * 16 + 255) / 256, 256>>>(M * 16);
    scatter_kernel<<<(E * 16 + 255) / 256, 256>>>(0, E, 16, 4);
    {
        dim3 grid((M + 255) / 256, 1);
        fused_gemm_kernel<<<grid, 256>>>(nullptr, 4, 0, rel1_w, root1_w,
                                         rel1_b, 1, M, 64, 64, 1);
    }

    // layer 2: agg(h1,64) ; h2 = relu(agg@rel2_w + rel2_b + h1@root2_w) -> buf 2
    zero_agg_kernel<<<(M * 16 + 255) / 256, 256>>>(M * 16);
    scatter_kernel<<<(E * 16 + 255) / 256, 256>>>(1, E, 16, 4);
    {
        dim3 grid((M + 255) / 256, 2);
        fused_gemm_kernel<<<grid, 256>>>(nullptr, 4, 1, rel2_w, root2_w,
                                         rel2_b, 2, M, 64, 128, 1);
    }

    // layer 3: agg(h2,128) ; h3 = relu(agg@rel3_w + rel3_b + h2@root3_w) -> buf 3
    zero_agg_kernel<<<(M * 32 + 255) / 256, 256>>>(M * 32);
    scatter_kernel<<<(E * 32 + 255) / 256, 256>>>(2, E, 32, 5);
    {
        dim3 grid((M + 255) / 256, 2);
        fused_gemm_kernel<<<grid, 256>>>(nullptr, 4, 2, rel3_w, root3_w,
                                         rel3_b, 3, M, 128, 128, 1);
    }

    // global mean pool + classifier
    zero_pool_kernel<<<(NUM_GRAPHS * 128 + 255) / 256, 256>>>();
    count_kernel<<<(M + 255) / 256, 256>>>(M);
    pool_kernel<<<(M * 32 + 255) / 256, 256>>>(M);
    final_kernel<<<NUM_GRAPHS, 16>>>(lin_w, lin_b, out);

    (void)n_in; (void)out_size;
}

// round 5
// speedup vs baseline: 1.9253x; 1.9253x over previous
#include <cuda_runtime.h>
#include <cstdint>

#define N_NODES 50000
#define N_EDGES 800000
#define NUM_GRAPHS 512

// ---------------- scratch (no allocations allowed) ----------------
__device__ __align__(16) float g_h0[N_NODES * 64];
__device__ __align__(16) float g_h1[N_NODES * 64];
__device__ __align__(16) float g_h2[N_NODES * 128];
__device__ __align__(16) float g_h3[N_NODES * 128];
__device__ __align__(16) float g_agg[N_NODES * 128];
__device__ __align__(16) float g_pool[NUM_GRAPHS * 128];
__device__ int   g_cnt[NUM_GRAPHS];
__device__ int   g_src[N_EDGES];
__device__ int   g_dst[N_EDGES];
__device__ int   g_batch[N_NODES];

__device__ __forceinline__ float* buf_ptr(int id) {
    switch (id) {
        case 0: return g_h0;
        case 1: return g_h1;
        case 2: return g_h2;
        case 3: return g_h3;
        default: return g_agg;
    }
}

// ---------------- index conversion (dtype-detecting) ----------------
__global__ void convert_edges_kernel(const void* __restrict__ ei_raw, int E) {
    const int* w = (const int*)ei_raw;
    bool is64 = true;
#pragma unroll
    for (int j = 1; j < 32; j += 2) is64 &= (w[j] == 0);
    int i = blockIdx.x * blockDim.x + threadIdx.x;
    if (i >= E) return;
    if (is64) {
        const long long* e64 = (const long long*)ei_raw;
        g_src[i] = (int)e64[i];
        g_dst[i] = (int)e64[E + i];
    } else {
        g_src[i] = w[i];
        g_dst[i] = w[E + i];
    }
}

__global__ void convert_batch_kernel(const void* __restrict__ b_raw, int N) {
    const int* w = (const int*)b_raw;
    bool is64 = true;
#pragma unroll
    for (int j = 0; j < 32; ++j) {
        int idx = N - 32 + j;
        if (idx & 1) is64 &= (w[idx] == 0);
    }
    int i = blockIdx.x * blockDim.x + threadIdx.x;
    if (i >= N) return;
    if (is64) g_batch[i] = (int)((const long long*)b_raw)[i];
    else      g_batch[i] = w[i];
}

// ---------------- small kernels ----------------
__global__ void zero_agg_kernel(int n4) {
    int i = blockIdx.x * blockDim.x + threadIdx.x;
    if (i < n4) ((float4*)g_agg)[i] = make_float4(0.f, 0.f, 0.f, 0.f);
}

__global__ void zero_pool_kernel() {
    int i = blockIdx.x * blockDim.x + threadIdx.x;
    if (i < NUM_GRAPHS * 128) g_pool[i] = 0.f;
    if (i < NUM_GRAPHS) g_cnt[i] = 0;
}

// ---------------- tf32 mma.sync GEMM ----------------
__device__ __forceinline__ float to_tf32(float x) {
    float y;
    asm("cvt.rna.tf32.f32 %0, %1;" : "=f"(y) : "f"(x));
    return y;
}
__device__ __forceinline__ void mma1688(float* d, const uint32_t* a, const uint32_t* b) {
    asm volatile(
        "mma.sync.aligned.m16n8k8.row.col.f32.tf32.tf32.f32 "
        "{%0,%1,%2,%3}, {%4,%5,%6,%7}, {%8,%9}, {%0,%1,%2,%3};\n"
        : "+f"(d[0]), "+f"(d[1]), "+f"(d[2]), "+f"(d[3])
        : "r"(a[0]), "r"(a[1]), "r"(a[2]), "r"(a[3]), "r"(b[0]), "r"(b[1]));
}

// out[M,NB] = relu?( A@Wa [+ B@Wb] + bias ); A/B fp32 [M,K] K-major, W [K,NB].
// CTA: 128 rows x NB cols; 8 warps in 4(M) x 2(N); K chunked by 64 through smem.
#define KC 64
#define LDA 68              // 64 + 4 pad: A frag banks = 4*grp + tig, conflict-free
template <int NB>
__global__ void __launch_bounds__(256, 2)
gemm_mma_kernel(const float* __restrict__ x_ext, int aId, int bId,
                const float* __restrict__ Wa, const float* __restrict__ Wb,
                const float* __restrict__ bias, int outId,
                int M, int Ka, int Kb, int doRelu) {
    constexpr int NI = NB / 16;   // 8-col frags per warp (half of NB per warp)
    constexpr int LDB = NB + 8;   // B frag banks = 8*tig + grp, conflict-free
    extern __shared__ float sm[];
    float* sA = sm;               // [128][LDA]
    float* sB = sm + 128 * LDA;   // [KC][LDB]

    int tid = threadIdx.x;
    int wid = tid >> 5, lane = tid & 31;
    int tig = lane & 3, grp = lane >> 2;
    int warp_m = wid & 3, warp_n = wid >> 2;
    int tile = blockIdx.x;
    int rowbase = tile * 128;
    int valid = M - rowbase; if (valid > 128) valid = 128;

    float acc[2][NI][4];
#pragma unroll
    for (int mi = 0; mi < 2; ++mi)
#pragma unroll
        for (int ni = 0; ni < NI; ++ni)
#pragma unroll
            for (int j = 0; j < 4; ++j) acc[mi][ni][j] = 0.f;

    const int npass = (Kb > 0) ? 2 : 1;
    for (int pass = 0; pass < npass; ++pass) {
        const float* X = pass ? buf_ptr(bId) : ((aId < 0) ? x_ext : buf_ptr(aId));
        const float* W = pass ? Wb : Wa;
        const int K = pass ? Kb : Ka;

        for (int kc = 0; kc < K; kc += KC) {
            __syncthreads();
            // load A chunk: 128 x 64 floats (zero-fill rows >= valid)
            for (int idx = tid; idx < 128 * 16; idx += 256) {
                int r = idx >> 4, k4 = (idx & 15) * 4;
                float4 v = make_float4(0.f, 0.f, 0.f, 0.f);
                if (r < valid)
                    v = *(const float4*)(X + (size_t)(rowbase + r) * K + kc + k4);
                float* p = sA + r * LDA + k4;
                p[0] = to_tf32(v.x); p[1] = to_tf32(v.y);
                p[2] = to_tf32(v.z); p[3] = to_tf32(v.w);
            }
            // load B chunk: W[kc..kc+64) x NB
            for (int idx = tid; idx < KC * (NB / 4); idx += 256) {
                int r = idx / (NB / 4), c4 = (idx - r * (NB / 4)) * 4;
                float4 v = *(const float4*)(W + (size_t)(kc + r) * NB + c4);
                float* p = sB + r * LDB + c4;
                p[0] = to_tf32(v.x); p[1] = to_tf32(v.y);
                p[2] = to_tf32(v.z); p[3] = to_tf32(v.w);
            }
            __syncthreads();

#pragma unroll
            for (int k8 = 0; k8 < KC / 8; ++k8) {
                int k0 = k8 * 8;
                uint32_t afr[2][4];
#pragma unroll
                for (int mi = 0; mi < 2; ++mi) {
                    int r0 = warp_m * 32 + mi * 16 + grp;
                    afr[mi][0] = __float_as_uint(sA[r0 * LDA + k0 + tig]);
                    afr[mi][1] = __float_as_uint(sA[(r0 + 8) * LDA + k0 + tig]);
                    afr[mi][2] = __float_as_uint(sA[r0 * LDA + k0 + tig + 4]);
                    afr[mi][3] = __float_as_uint(sA[(r0 + 8) * LDA + k0 + tig + 4]);
                }
                uint32_t bfr[NI][2];
#pragma unroll
                for (int ni = 0; ni < NI; ++ni) {
                    int c = warp_n * (NB / 2) + ni * 8 + grp;
                    bfr[ni][0] = __float_as_uint(sB[(k0 + tig) * LDB + c]);
                    bfr[ni][1] = __float_as_uint(sB[(k0 + tig + 4) * LDB + c]);
                }
#pragma unroll
                for (int mi = 0; mi < 2; ++mi)
#pragma unroll
                    for (int ni = 0; ni < NI; ++ni)
                        mma1688(acc[mi][ni], afr[mi], bfr[ni]);
            }
        }
    }

    // epilogue: bias + relu, float2 stores
    float* outp = buf_ptr(outId);
#pragma unroll
    for (int mi = 0; mi < 2; ++mi) {
        int r0 = rowbase + warp_m * 32 + mi * 16 + grp;
#pragma unroll
        for (int ni = 0; ni < NI; ++ni) {
            int c = warp_n * (NB / 2) + ni * 8 + tig * 2;
            float b0 = bias[c], b1 = bias[c + 1];
            if (r0 < M) {
                float2 v = make_float2(acc[mi][ni][0] + b0, acc[mi][ni][1] + b1);
                if (doRelu) { v.x = fmaxf(v.x, 0.f); v.y = fmaxf(v.y, 0.f); }
                *(float2*)(outp + (size_t)r0 * NB + c) = v;
            }
            if (r0 + 8 < M) {
                float2 v = make_float2(acc[mi][ni][2] + b0, acc[mi][ni][3] + b1);
                if (doRelu) { v.x = fmaxf(v.x, 0.f); v.y = fmaxf(v.y, 0.f); }
                *(float2*)(outp + (size_t)(r0 + 8) * NB + c) = v;
            }
        }
    }
}

// ---------------- scatter / pool / classifier ----------------
__global__ void scatter_kernel(int hId, int E, int dimv, int lg) {
    int idx = blockIdx.x * blockDim.x + threadIdx.x;
    if (idx >= E * dimv) return;
    const float* h = buf_ptr(hId);
    int e = idx >> lg;
    int c = idx & (dimv - 1);
    int s = g_src[e];
    int d = g_dst[e];
    float4 v = ((const float4*)h)[(size_t)s * dimv + c];
    float* p = g_agg + (((size_t)d * dimv + c) << 2);
    asm volatile("red.global.add.v4.f32 [%0], {%1, %2, %3, %4};"
                 :: "l"(p), "f"(v.x), "f"(v.y), "f"(v.z), "f"(v.w) : "memory");
}

__global__ void count_kernel(int N) {
    int i = blockIdx.x * blockDim.x + threadIdx.x;
    if (i < N) atomicAdd(&g_cnt[g_batch[i]], 1);
}

__global__ void pool_kernel(int N) {
    int idx = blockIdx.x * blockDim.x + threadIdx.x;
    if (idx >= N * 32) return;
    int node = idx >> 5;
    int c = idx & 31;
    int g = g_batch[node];
    float4 v = ((const float4*)g_h3)[(size_t)node * 32 + c];
    float* p = g_pool + (((size_t)g * 32 + c) << 2);
    asm volatile("red.global.add.v4.f32 [%0], {%1, %2, %3, %4};"
                 :: "l"(p), "f"(v.x), "f"(v.y), "f"(v.z), "f"(v.w) : "memory");
}

__global__ void final_kernel(const float* __restrict__ lw, const float* __restrict__ lb,
                             float* __restrict__ out) {
    int g = blockIdx.x;
    int c = threadIdx.x;  // 16
    float inv = 1.f / fmaxf((float)g_cnt[g], 1.f);
    float acc = lb[c];
#pragma unroll 8
    for (int k = 0; k < 128; ++k)
        acc += g_pool[g * 128 + k] * inv * lw[k * 16 + c];
    out[g * 16 + c] = acc;
}

// ---------------- launch ----------------
extern "C" void kernel_launch(void* const* d_in, const int* in_sizes, int n_in,
                              void* d_out, int out_size) {
    const float* x     = (const float*)d_in[0];
    const void*  ei    = d_in[1];
    const void*  batch = d_in[2];
    int wi = (in_sizes[3] < 100) ? 4 : 3;
    const float* w_stage1 = (const float*)d_in[wi + 0];
    const float* b_stage1 = (const float*)d_in[wi + 1];
    const float* rel1_w   = (const float*)d_in[wi + 2];
    const float* rel1_b   = (const float*)d_in[wi + 3];
    const float* root1_w  = (const float*)d_in[wi + 4];
    const float* rel2_w   = (const float*)d_in[wi + 5];
    const float* rel2_b   = (const float*)d_in[wi + 6];
    const float* root2_w  = (const float*)d_in[wi + 7];
    const float* rel3_w   = (const float*)d_in[wi + 8];
    const float* rel3_b   = (const float*)d_in[wi + 9];
    const float* root3_w  = (const float*)d_in[wi + 10];
    const float* lin_w    = (const float*)d_in[wi + 11];
    const float* lin_b    = (const float*)d_in[wi + 12];
    float* out = (float*)d_out;

    const int M = N_NODES, E = N_EDGES;
    const int MT = (M + 127) / 128;  // 391 M-tiles

    const int smem64  = (128 * LDA + KC * (64 + 8)) * 4;
    const int smem128 = (128 * LDA + KC * (128 + 8)) * 4;
    cudaFuncSetAttribute(gemm_mma_kernel<64>,
                         cudaFuncAttributeMaxDynamicSharedMemorySize, smem64);
    cudaFuncSetAttribute(gemm_mma_kernel<128>,
                         cudaFuncAttributeMaxDynamicSharedMemorySize, smem128);

    convert_edges_kernel<<<(E + 255) / 256, 256>>>(ei, E);
    convert_batch_kernel<<<(M + 255) / 256, 256>>>(batch, M);

    // stage1: h0 = x @ w_stage1 + b_stage1 -> buf 0  [K=128, N=64]
    gemm_mma_kernel<64><<<MT, 256, smem64>>>(x, -1, -1, w_stage1, nullptr,
                                             b_stage1, 0, M, 128, 0, 0);

    // layer 1: agg(h0,64); h1 = relu(agg@rel1 + h0@root1 + b) -> buf 1 [N=64]
    zero_agg_kernel<<<(M * 16 + 255) / 256, 256>>>(M * 16);
    scatter_kernel<<<(E * 16 + 255) / 256, 256>>>(0, E, 16, 4);
    gemm_mma_kernel<64><<<MT, 256, smem64>>>(nullptr, 4, 0, rel1_w, root1_w,
                                             rel1_b, 1, M, 64, 64, 1);

    // layer 2: agg(h1,64); h2 = relu(agg@rel2 + h1@root2 + b) -> buf 2 [N=128]
    zero_agg_kernel<<<(M * 16 + 255) / 256, 256>>>(M * 16);
    scatter_kernel<<<(E * 16 + 255) / 256, 256>>>(1, E, 16, 4);
    gemm_mma_kernel<128><<<MT, 256, smem128>>>(nullptr, 4, 1, rel2_w, root2_w,
                                               rel2_b, 2, M, 64, 64, 1);

    // layer 3: agg(h2,128); h3 = relu(agg@rel3 + h2@root3 + b) -> buf 3 [N=128]
    zero_agg_kernel<<<(M * 32 + 255) / 256, 256>>>(M * 32);
    scatter_kernel<<<(E * 32 + 255) / 256, 256>>>(2, E, 32, 5);
    gemm_mma_kernel<128><<<MT, 256, smem128>>>(nullptr, 4, 2, rel3_w, root3_w,
                                               rel3_b, 3, M, 128, 128, 1);

    // global mean pool + classifier
    zero_pool_kernel<<<(NUM_GRAPHS * 128 + 255) / 256, 256>>>();
    count_kernel<<<(M + 255) / 256, 256>>>(M);
    pool_kernel<<<(M * 32 + 255) / 256, 256>>>(M);
    final_kernel<<<NUM_GRAPHS, 16>>>(lin_w, lin_b, out);

    (void)n_in; (void)out_size;
}

// round 6
// speedup vs baseline: 2.2440x; 1.1656x over previous
#include <cuda_runtime.h>
#include <cstdint>

#define N_NODES 50000
#define N_EDGES 800000
#define NUM_GRAPHS 512
#define NBLK 49  // ceil(50000/1024)

// ---------------- scratch (no allocations allowed) ----------------
__device__ __align__(16) float g_h0[N_NODES * 64];
__device__ __align__(16) float g_h1[N_NODES * 64];
__device__ __align__(16) float g_h2[N_NODES * 128];
__device__ __align__(16) float g_agg[N_NODES * 128];
__device__ __align__(16) float g_pool[NUM_GRAPHS * 128];
__device__ int   g_cnt[NUM_GRAPHS];
__device__ int   g_src[N_EDGES];
__device__ int   g_dst[N_EDGES];
__device__ int   g_batch[N_NODES];
__device__ int   g_deg[N_NODES];
__device__ int   g_off[N_NODES + 1];
__device__ int   g_fill[N_NODES];
__device__ int   g_csr[N_EDGES];
__device__ int   g_bsum[NBLK];
__device__ int   g_bpre[NBLK];

__device__ __forceinline__ float* buf_ptr(int id) {
    switch (id) {
        case 0: return g_h0;
        case 1: return g_h1;
        case 2: return g_h2;
        default: return g_agg;
    }
}

// ---------------- index conversion (dtype-detecting) ----------------
__global__ void convert_edges_kernel(const void* __restrict__ ei_raw, int E) {
    const int* w = (const int*)ei_raw;
    bool is64 = true;
#pragma unroll
    for (int j = 1; j < 32; j += 2) is64 &= (w[j] == 0);
    int i = blockIdx.x * blockDim.x + threadIdx.x;
    if (i >= E) return;
    if (is64) {
        const long long* e64 = (const long long*)ei_raw;
        g_src[i] = (int)e64[i];
        g_dst[i] = (int)e64[E + i];
    } else {
        g_src[i] = w[i];
        g_dst[i] = w[E + i];
    }
}

__global__ void convert_batch_kernel(const void* __restrict__ b_raw, int N) {
    const int* w = (const int*)b_raw;
    bool is64 = true;
#pragma unroll
    for (int j = 0; j < 32; ++j) {
        int idx = N - 32 + j;
        if (idx & 1) is64 &= (w[idx] == 0);
    }
    int i = blockIdx.x * blockDim.x + threadIdx.x;
    if (i >= N) return;
    if (is64) g_batch[i] = (int)((const long long*)b_raw)[i];
    else      g_batch[i] = w[i];
}

// ---------------- CSR build ----------------
__global__ void init_kernel() {
    int i = blockIdx.x * blockDim.x + threadIdx.x;
    if (i < N_NODES) g_deg[i] = 0;
    if (i < NUM_GRAPHS * 128) g_pool[i] = 0.f;
    if (i < NUM_GRAPHS) g_cnt[i] = 0;
}

__global__ void hist_kernel(int E) {
    int i = blockIdx.x * blockDim.x + threadIdx.x;
    if (i < E) atomicAdd(&g_deg[g_dst[i]], 1);
}

__global__ void scan1_kernel() {
    __shared__ int s[1024];
    int t = threadIdx.x;
    int i = blockIdx.x * 1024 + t;
    int v = (i < N_NODES) ? g_deg[i] : 0;
    s[t] = v; __syncthreads();
#pragma unroll
    for (int d = 1; d < 1024; d <<= 1) {
        int y = (t >= d) ? s[t - d] : 0;
        __syncthreads();
        s[t] += y;
        __syncthreads();
    }
    if (i < N_NODES) g_off[i] = s[t] - v;   // block-local exclusive
    if (t == 1023) g_bsum[blockIdx.x] = s[1023];
}

__global__ void scan2_kernel() {
    __shared__ int s[64];
    int t = threadIdx.x;
    int v = (t < NBLK) ? g_bsum[t] : 0;
    s[t] = v; __syncthreads();
#pragma unroll
    for (int d = 1; d < 64; d <<= 1) {
        int y = (t >= d) ? s[t - d] : 0;
        __syncthreads();
        s[t] += y;
        __syncthreads();
    }
    if (t < NBLK) g_bpre[t] = s[t] - v;
    if (t == 63) g_off[N_NODES] = s[63];
}

__global__ void scan3_kernel() {
    int i = blockIdx.x * blockDim.x + threadIdx.x;
    if (i < N_NODES) {
        int o = g_off[i] + g_bpre[i >> 10];
        g_off[i] = o;
        g_fill[i] = o;
    }
}

__global__ void fill_kernel(int E) {
    int i = blockIdx.x * blockDim.x + threadIdx.x;
    if (i < E) {
        int p = atomicAdd(&g_fill[g_dst[i]], 1);
        g_csr[p] = g_src[i];
    }
}

// ---------------- CSR gather: agg[n] = sum_{s in N(n)} h[s] ----------------
template <int DIMV>   // DIMV = dim/4 lanes per node (16 or 32)
__global__ void gather_kernel(int hId, int N) {
    int gt = blockIdx.x * blockDim.x + threadIdx.x;
    int gid = gt / DIMV;
    int lane = gt & (DIMV - 1);
    if (gid >= N) return;
    const float4* h = (const float4*)buf_ptr(hId);
    int e = g_off[gid], end = g_off[gid + 1];
    float4 acc = make_float4(0.f, 0.f, 0.f, 0.f);
    for (; e + 1 < end; e += 2) {
        int s0 = g_csr[e], s1 = g_csr[e + 1];
        float4 v0 = h[(size_t)s0 * DIMV + lane];
        float4 v1 = h[(size_t)s1 * DIMV + lane];
        acc.x += v0.x; acc.y += v0.y; acc.z += v0.z; acc.w += v0.w;
        acc.x += v1.x; acc.y += v1.y; acc.z += v1.z; acc.w += v1.w;
    }
    if (e < end) {
        int s0 = g_csr[e];
        float4 v0 = h[(size_t)s0 * DIMV + lane];
        acc.x += v0.x; acc.y += v0.y; acc.z += v0.z; acc.w += v0.w;
    }
    ((float4*)g_agg)[(size_t)gid * DIMV + lane] = acc;
}

// ---------------- tf32 mma.sync GEMM ----------------
__device__ __forceinline__ float to_tf32(float x) {
    float y;
    asm("cvt.rna.tf32.f32 %0, %1;" : "=f"(y) : "f"(x));
    return y;
}
__device__ __forceinline__ void mma1688(float* d, const uint32_t* a, const uint32_t* b) {
    asm volatile(
        "mma.sync.aligned.m16n8k8.row.col.f32.tf32.tf32.f32 "
        "{%0,%1,%2,%3}, {%4,%5,%6,%7}, {%8,%9}, {%0,%1,%2,%3};\n"
        : "+f"(d[0]), "+f"(d[1]), "+f"(d[2]), "+f"(d[3])
        : "r"(a[0]), "r"(a[1]), "r"(a[2]), "r"(a[3]), "r"(b[0]), "r"(b[1]));
}

#define KC 64
#define LDA 68
// out = relu?( A@Wa [+ B@Wb] + bias ). poolMode: reduce relu(out) rows into
// g_pool[batch[row]] via per-CTA smem accumulation instead of storing out.
template <int NB>
__global__ void __launch_bounds__(256, 2)
gemm_mma_kernel(const float* __restrict__ x_ext, int aId, int bId,
                const float* __restrict__ Wa, const float* __restrict__ Wb,
                const float* __restrict__ bias, int outId,
                int M, int Ka, int Kb, int doRelu, int poolMode) {
    constexpr int NI = NB / 16;
    constexpr int LDB = NB + 8;
    extern __shared__ float sm[];
    float* sA = sm;               // [128][LDA]
    float* sB = sm + 128 * LDA;   // [KC][LDB]

    int tid = threadIdx.x;
    int wid = tid >> 5, lane = tid & 31;
    int tig = lane & 3, grp = lane >> 2;
    int warp_m = wid & 3, warp_n = wid >> 2;
    int tile = blockIdx.x;
    int rowbase = tile * 128;
    int valid = M - rowbase; if (valid > 128) valid = 128;

    float acc[2][NI][4];
#pragma unroll
    for (int mi = 0; mi < 2; ++mi)
#pragma unroll
        for (int ni = 0; ni < NI; ++ni)
#pragma unroll
            for (int j = 0; j < 4; ++j) acc[mi][ni][j] = 0.f;

    const int npass = (Kb > 0) ? 2 : 1;
    for (int pass = 0; pass < npass; ++pass) {
        const float* X = pass ? buf_ptr(bId) : ((aId < 0) ? x_ext : buf_ptr(aId));
        const float* W = pass ? Wb : Wa;
        const int K = pass ? Kb : Ka;

        for (int kc = 0; kc < K; kc += KC) {
            __syncthreads();
            for (int idx = tid; idx < 128 * 16; idx += 256) {
                int r = idx >> 4, k4 = (idx & 15) * 4;
                float4 v = make_float4(0.f, 0.f, 0.f, 0.f);
                if (r < valid)
                    v = *(const float4*)(X + (size_t)(rowbase + r) * K + kc + k4);
                float* p = sA + r * LDA + k4;
                p[0] = to_tf32(v.x); p[1] = to_tf32(v.y);
                p[2] = to_tf32(v.z); p[3] = to_tf32(v.w);
            }
            for (int idx = tid; idx < KC * (NB / 4); idx += 256) {
                int r = idx / (NB / 4), c4 = (idx - r * (NB / 4)) * 4;
                float4 v = *(const float4*)(W + (size_t)(kc + r) * NB + c4);
                float* p = sB + r * LDB + c4;
                p[0] = to_tf32(v.x); p[1] = to_tf32(v.y);
                p[2] = to_tf32(v.z); p[3] = to_tf32(v.w);
            }
            __syncthreads();

#pragma unroll
            for (int k8 = 0; k8 < KC / 8; ++k8) {
                int k0 = k8 * 8;
                uint32_t afr[2][4];
#pragma unroll
                for (int mi = 0; mi < 2; ++mi) {
                    int r0 = warp_m * 32 + mi * 16 + grp;
                    afr[mi][0] = __float_as_uint(sA[r0 * LDA + k0 + tig]);
                    afr[mi][1] = __float_as_uint(sA[(r0 + 8) * LDA + k0 + tig]);
                    afr[mi][2] = __float_as_uint(sA[r0 * LDA + k0 + tig + 4]);
                    afr[mi][3] = __float_as_uint(sA[(r0 + 8) * LDA + k0 + tig + 4]);
                }
                uint32_t bfr[NI][2];
#pragma unroll
                for (int ni = 0; ni < NI; ++ni) {
                    int c = warp_n * (NB / 2) + ni * 8 + grp;
                    bfr[ni][0] = __float_as_uint(sB[(k0 + tig) * LDB + c]);
                    bfr[ni][1] = __float_as_uint(sB[(k0 + tig + 4) * LDB + c]);
                }
#pragma unroll
                for (int mi = 0; mi < 2; ++mi)
#pragma unroll
                    for (int ni = 0; ni < NI; ++ni)
                        mma1688(acc[mi][ni], afr[mi], bfr[ni]);
            }
        }
    }

    if (!poolMode) {
        float* outp = buf_ptr(outId);
#pragma unroll
        for (int mi = 0; mi < 2; ++mi) {
            int r0 = rowbase + warp_m * 32 + mi * 16 + grp;
#pragma unroll
            for (int ni = 0; ni < NI; ++ni) {
                int c = warp_n * (NB / 2) + ni * 8 + tig * 2;
                float b0 = bias[c], b1 = bias[c + 1];
                if (r0 < M) {
                    float2 v = make_float2(acc[mi][ni][0] + b0, acc[mi][ni][1] + b1);
                    if (doRelu) { v.x = fmaxf(v.x, 0.f); v.y = fmaxf(v.y, 0.f); }
                    *(float2*)(outp + (size_t)r0 * NB + c) = v;
                }
                if (r0 + 8 < M) {
                    float2 v = make_float2(acc[mi][ni][2] + b0, acc[mi][ni][3] + b1);
                    if (doRelu) { v.x = fmaxf(v.x, 0.f); v.y = fmaxf(v.y, 0.f); }
                    *(float2*)(outp + (size_t)(r0 + 8) * NB + c) = v;
                }
            }
        }
    } else {
        // pooled epilogue: sorted batch -> a 128-row tile spans few graphs.
        __shared__ float spool[8][NB];
        for (int idx = tid; idx < 8 * NB; idx += 256) ((float*)spool)[idx] = 0.f;
        __syncthreads();
        int gmin = g_batch[rowbase];
#pragma unroll
        for (int mi = 0; mi < 2; ++mi) {
            int r0 = rowbase + warp_m * 32 + mi * 16 + grp;
#pragma unroll
            for (int rr = 0; rr < 2; ++rr) {
                int r = r0 + rr * 8;
                if (r >= M) continue;
                int dg = g_batch[r] - gmin;
#pragma unroll
                for (int ni = 0; ni < NI; ++ni) {
                    int c = warp_n * (NB / 2) + ni * 8 + tig * 2;
                    float vx = fmaxf(acc[mi][ni][rr * 2 + 0] + bias[c], 0.f);
                    float vy = fmaxf(acc[mi][ni][rr * 2 + 1] + bias[c + 1], 0.f);
                    if (dg < 8) {
                        atomicAdd(&spool[dg][c], vx);
                        atomicAdd(&spool[dg][c + 1], vy);
                    } else {  // safety fallback (practically unreachable)
                        asm volatile("red.global.add.f32 [%0], %1;"
                                     :: "l"(&g_pool[(size_t)(gmin + dg) * 128 + c]), "f"(vx) : "memory");
                        asm volatile("red.global.add.f32 [%0], %1;"
                                     :: "l"(&g_pool[(size_t)(gmin + dg) * 128 + c + 1]), "f"(vy) : "memory");
                    }
                }
            }
        }
        __syncthreads();
        int gmax = g_batch[rowbase + valid - 1];
        int span = gmax - gmin + 1; if (span > 8) span = 8;
        for (int idx = tid; idx < span * (NB / 4); idx += 256) {
            int gg = idx / (NB / 4), c4 = (idx - gg * (NB / 4)) * 4;
            float4 v = *(float4*)&spool[gg][c4];
            float* p = &g_pool[(size_t)(gmin + gg) * 128 + c4];
            asm volatile("red.global.add.v4.f32 [%0], {%1, %2, %3, %4};"
                         :: "l"(p), "f"(v.x), "f"(v.y), "f"(v.z), "f"(v.w) : "memory");
        }
    }
}

// ---------------- pool count / classifier ----------------
__global__ void count_kernel(int N) {
    int i = blockIdx.x * blockDim.x + threadIdx.x;
    if (i < N) atomicAdd(&g_cnt[g_batch[i]], 1);
}

__global__ void final_kernel(const float* __restrict__ lw, const float* __restrict__ lb,
                             float* __restrict__ out) {
    int g = blockIdx.x;
    int c = threadIdx.x;  // 16
    float inv = 1.f / fmaxf((float)g_cnt[g], 1.f);
    float acc = lb[c];
#pragma unroll 8
    for (int k = 0; k < 128; ++k)
        acc += g_pool[g * 128 + k] * inv * lw[k * 16 + c];
    out[g * 16 + c] = acc;
}

// ---------------- launch ----------------
extern "C" void kernel_launch(void* const* d_in, const int* in_sizes, int n_in,
                              void* d_out, int out_size) {
    const float* x     = (const float*)d_in[0];
    const void*  ei    = d_in[1];
    const void*  batch = d_in[2];
    int wi = (in_sizes[3] < 100) ? 4 : 3;
    const float* w_stage1 = (const float*)d_in[wi + 0];
    const float* b_stage1 = (const float*)d_in[wi + 1];
    const float* rel1_w   = (const float*)d_in[wi + 2];
    const float* rel1_b   = (const float*)d_in[wi + 3];
    const float* root1_w  = (const float*)d_in[wi + 4];
    const float* rel2_w   = (const float*)d_in[wi + 5];
    const float* rel2_b   = (const float*)d_in[wi + 6];
    const float* root2_w  = (const float*)d_in[wi + 7];
    const float* rel3_w   = (const float*)d_in[wi + 8];
    const float* rel3_b   = (const float*)d_in[wi + 9];
    const float* root3_w  = (const float*)d_in[wi + 10];
    const float* lin_w    = (const float*)d_in[wi + 11];
    const float* lin_b    = (const float*)d_in[wi + 12];
    float* out = (float*)d_out;

    const int M = N_NODES, E = N_EDGES;
    const int MT = (M + 127) / 128;

    const int smem64  = (128 * LDA + KC * (64 + 8)) * 4;
    const int smem128 = (128 * LDA + KC * (128 + 8)) * 4;
    cudaFuncSetAttribute(gemm_mma_kernel<64>,
                         cudaFuncAttributeMaxDynamicSharedMemorySize, smem64);
    cudaFuncSetAttribute(gemm_mma_kernel<128>,
                         cudaFuncAttributeMaxDynamicSharedMemorySize, smem128);

    // index conversion + CSR build
    convert_edges_kernel<<<(E + 255) / 256, 256>>>(ei, E);
    convert_batch_kernel<<<(M + 255) / 256, 256>>>(batch, M);
    init_kernel<<<(NUM_GRAPHS * 128 + 255) / 256 + 200, 256>>>();
    hist_kernel<<<(E + 255) / 256, 256>>>(E);
    scan1_kernel<<<NBLK, 1024>>>();
    scan2_kernel<<<1, 64>>>();
    scan3_kernel<<<(M + 255) / 256, 256>>>();
    fill_kernel<<<(E + 255) / 256, 256>>>(E);
    count_kernel<<<(M + 255) / 256, 256>>>(M);

    // stage1: h0 = x @ w_stage1 + b_stage1 -> buf 0  [K=128, N=64]
    gemm_mma_kernel<64><<<MT, 256, smem64>>>(x, -1, -1, w_stage1, nullptr,
                                             b_stage1, 0, M, 128, 0, 0, 0);

    // layer 1
    gather_kernel<16><<<(M * 16 + 255) / 256, 256>>>(0, M);
    gemm_mma_kernel<64><<<MT, 256, smem64>>>(nullptr, 3, 0, rel1_w, root1_w,
                                             rel1_b, 1, M, 64, 64, 1, 0);

    // layer 2
    gather_kernel<16><<<(M * 16 + 255) / 256, 256>>>(1, M);
    gemm_mma_kernel<128><<<MT, 256, smem128>>>(nullptr, 3, 1, rel2_w, root2_w,
                                               rel2_b, 2, M, 64, 64, 1, 0);

    // layer 3 (pooled epilogue; h3 never materialized)
    gather_kernel<32><<<(M * 32 + 255) / 256, 256>>>(2, M);
    gemm_mma_kernel<128><<<MT, 256, smem128>>>(nullptr, 3, 2, rel3_w, root3_w,
                                               rel3_b, 0, M, 128, 128, 1, 1);

    final_kernel<<<NUM_GRAPHS, 16>>>(lin_w, lin_b, out);

    (void)n_in; (void)out_size;
}